// round 9
// baseline (speedup 1.0000x reference)
#include <cuda_runtime.h>
#include <cuda_bf16.h>
#include <math.h>
#include <stdint.h>

// Problem constants
#define NN 13
#define BB 2
#define TT 2048
#define DD 1024
#define ROW_F4 (DD / 4)          // 256 float4 per row
#define NTILES (BB * TT)         // 4096
#define THREADS 256
#define GRID 304                 // 2 CTAs per SM
#define EPS 1.1920928955078125e-07f   // FLT_EPSILON

// Dynamic smem: 2 row buffers x NN x 256 float4 = 106496 B
#define BUF_F4      (NN * ROW_F4)
#define SMEM_BYTES  (2 * BUF_F4 * 16)

__device__ __forceinline__ void cp_async16(uint32_t smem_addr, const void* gptr) {
    asm volatile("cp.async.cg.shared.global [%0], [%1], 16;\n"
                 :: "r"(smem_addr), "l"(gptr) : "memory");
}

__global__ __launch_bounds__(THREADS, 2)
void attn_res_block_kernel(const float4* __restrict__ V,
                           const float4* __restrict__ rms_w,
                           const float4* __restrict__ w_proj,
                           float4* __restrict__ out)
{
    extern __shared__ float4 sbuf[];            // [2][NN][ROW_F4]
    __shared__ float4 s_cw[ROW_F4];             // combined weights (4 KB)
    __shared__ float  s_logit[NN];

    const int tid  = threadIdx.x;
    const int lane = tid & 31;
    const int wid  = tid >> 5;

    uint32_t sb_a;
    {
        uint64_t t;
        asm("cvta.to.shared.u64 %0, %1;" : "=l"(t) : "l"((void*)sbuf));
        sb_a = (uint32_t)t;
    }

    // Combined weight (rms_weight * w_proj) -> smem, computed once.
    // Visible to phase 1 after the first iteration's B0 barrier.
    {
        float4 a = rms_w[tid];
        float4 b = w_proj[tid];
        s_cw[tid] = make_float4(a.x * b.x, a.y * b.y, a.z * b.z, a.w * b.w);
    }

#define ISSUE_TILE(t, pbuf)                                                  \
    {                                                                        \
        const float4* g = V + (long)(t) * ROW_F4 + tid;                      \
        uint32_t s = sb_a + (uint32_t)((pbuf) * BUF_F4 + tid) * 16u;         \
        _Pragma("unroll")                                                    \
        for (int n = 0; n < NN; n++)                                         \
            cp_async16(s + (uint32_t)n * (ROW_F4 * 16u),                     \
                       (const void*)(g + (long)n * (NTILES * ROW_F4)));      \
        asm volatile("cp.async.commit_group;\n" ::: "memory");               \
    }

    int tile = blockIdx.x;
    int p = 0;

    // Prologue: two tiles in flight.
    ISSUE_TILE(tile, 0)
    if (tile + GRID < NTILES) ISSUE_TILE(tile + GRID, 1)

    while (tile < NTILES) {
        if (tile + GRID < NTILES)
            asm volatile("cp.async.wait_group 1;\n" ::: "memory");
        else
            asm volatile("cp.async.wait_group 0;\n" ::: "memory");
        __syncthreads();   // B0: tile i fully visible to all threads

        const float4* cur = sbuf + p * BUF_F4;

        // ---- Phase 1 (row-mapped): warp w owns rows w and w+8.
        // Conflict-free strided LDS; full dual reduce in-warp -> logit.
        #pragma unroll
        for (int rep = 0; rep < 2; rep++) {
            const int r = wid + rep * 8;
            if (r < NN) {
                float tss = 0.f, tdp = 0.f;
                #pragma unroll
                for (int k = 0; k < 8; k++) {
                    float4 x = cur[r * ROW_F4 + k * 32 + lane];
                    float4 w = s_cw[k * 32 + lane];
                    tss = fmaf(x.x, x.x, fmaf(x.y, x.y, fmaf(x.z, x.z, fmaf(x.w, x.w, tss))));
                    tdp = fmaf(x.x, w.x, fmaf(x.y, w.y, fmaf(x.z, w.z, fmaf(x.w, w.w, tdp))));
                }
                #pragma unroll
                for (int off = 16; off > 0; off >>= 1) {
                    tss += __shfl_xor_sync(0xFFFFFFFFu, tss, off);
                    tdp += __shfl_xor_sync(0xFFFFFFFFu, tdp, off);
                }
                if (lane == 0)
                    s_logit[r] = rsqrtf(tss * (1.0f / DD) + EPS) * tdp;
            }
        }
        __syncthreads();   // B1: logits valid; ALL phase-1 reads of buffer p done

        // ---- Detach this thread's column into registers (thread-private
        // cells [n][tid], written by this thread's own cp.async).
        float4 v[NN];
        #pragma unroll
        for (int n = 0; n < NN; n++)
            v[n] = cur[n * ROW_F4 + tid];

        // ---- Refill buffer p with tile i+2 NOW — ~800 cyc earlier than
        // end-of-iteration. The LDS above issued before these LDGSTS and the
        // copy engine cannot write back sooner than L2 latency, so the old
        // values are safely captured.
        if (tile + 2 * GRID < NTILES) ISSUE_TILE(tile + 2 * GRID, p)

        // ---- Softmax: per-warp, redundant (no extra barrier).
        float lv = (lane < NN) ? s_logit[lane] : -INFINITY;
        float mx = lv;
        #pragma unroll
        for (int off = 16; off > 0; off >>= 1)
            mx = fmaxf(mx, __shfl_xor_sync(0xFFFFFFFFu, mx, off));
        float e = (lane < NN) ? __expf(lv - mx) : 0.f;
        float sm = e;
        #pragma unroll
        for (int off = 16; off > 0; off >>= 1)
            sm += __shfl_xor_sync(0xFFFFFFFFu, sm, off);
        const float av = e * (1.0f / sm);     // alpha for depth = lane

        // ---- Phase 2: weighted sum from registers; alphas via shuffle bcast.
        float4 o = make_float4(0.f, 0.f, 0.f, 0.f);
        #pragma unroll
        for (int n = 0; n < NN; n++) {
            float an = __shfl_sync(0xFFFFFFFFu, av, n);
            o.x = fmaf(an, v[n].x, o.x);
            o.y = fmaf(an, v[n].y, o.y);
            o.z = fmaf(an, v[n].z, o.z);
            o.w = fmaf(an, v[n].w, o.w);
        }
        out[(long)tile * ROW_F4 + tid] = o;

        tile += GRID;
        p ^= 1;
    }
#undef ISSUE_TILE
}

extern "C" void kernel_launch(void* const* d_in, const int* in_sizes, int n_in,
                              void* d_out, int out_size)
{
    const float4* V      = (const float4*)d_in[0];   // [13,2,2048,1024] f32
    const float4* rms_w  = (const float4*)d_in[1];   // [1024] f32
    const float4* w_proj = (const float4*)d_in[2];   // [1024] f32
    float4* out          = (float4*)d_out;           // [2,2048,1024] f32

    cudaFuncSetAttribute(attn_res_block_kernel,
                         cudaFuncAttributeMaxDynamicSharedMemorySize, SMEM_BYTES);

    attn_res_block_kernel<<<GRID, THREADS, SMEM_BYTES>>>(V, rms_w, w_proj, out);
}